// round 16
// baseline (speedup 1.0000x reference)
#include <cuda_runtime.h>
#include <cuda_fp16.h>
#include <cstdint>
#include <cstddef>

// LSTM: B == H == 1024, S = 128, I = 1024. Persistent kernel.
// Per step: gates = x_s @ Wx + h_{s-1} @ Wh + bias (64 BK=32 slabs: 32 x, 32 h).
// x-phase: A comes via LDG.128 from fragment-linear g_XT (no smem for A);
// h-phase: A via smem as before. B always via bulk ring + ldmatrix.
// Group-of-4-slab transfers on one tx-mbarrier; producer warp drives bulk
// copies, h store + per-row grid barrier overlapped with x-GEMM.
// fp16 single-product mma.sync; col' = 4n+g (i,f,g,o).

#define HID  1024
#define SLEN 128
#define NGC  4096

#define BM 128
#define BN 256
#define BK 32
#define NSX 32               // x slabs per step (also h slabs per step)
#define GRP 4                // slabs per transfer group

#define A_TILE_B 8192        // 128 x 32 fp16
#define B_TILE_B 16384       // 256 x 32 fp16
#define STAGE_B  (A_TILE_B + B_TILE_B)   // 24576
#define GROUP_B  (GRP * STAGE_B)         // 98304
#define RING_B   (2 * GROUP_B)           // 196608
#define HSTG_OFF RING_B
#define HSTG_B   (2 * A_TILE_B)          // CTA's h slice = 16KB
#define SMEM_P   (RING_B + 2 * HSTG_B)   // 229376

#define A_SLAB_H 4096
#define B_SLAB_H 8192
#define MT_H (NSX * A_SLAB_H)   // 131072 halfs per h m-tile
#define NT_H (NSX * B_SLAB_H)   // 262144 halfs per B n-tile

#define ROW_CTAS 16
#define NCW 16
#define THREADS (NCW * 32 + 32)  // 544

// ---- static device scratch (each < 2GB) ----
__device__ __align__(1024) __half g_WhT[(size_t)16 * NT_H];          // 8 MB
__device__ __align__(1024) __half g_WxT[(size_t)16 * NT_H];          // 8 MB
// x in mma-fragment-linear layout: [mtile(8)][s(128)][slab(32)][wm(4)][lane(32)][4x16B]
__device__ __align__(1024) __half g_XT[(size_t)8 * SLEN * MT_H];     // 256 MB
__device__ __align__(1024) __half g_HaT[2][(size_t)8 * MT_H];        // 2 MB each
__device__ float g_bias[NGC];
__device__ unsigned g_cnt[8];

// ---- helpers ----
__device__ __forceinline__ uint32_t smem_u32(const void* p) {
    uint32_t a;
    asm("{ .reg .u64 t; cvta.to.shared.u64 t, %1; cvt.u32.u64 %0, t; }" : "=r"(a) : "l"(p));
    return a;
}
__device__ __forceinline__ void mbar_init(uint32_t bar, uint32_t cnt) {
    asm volatile("mbarrier.init.shared.b64 [%0], %1;" :: "r"(bar), "r"(cnt) : "memory");
}
__device__ __forceinline__ void mbar_arrive(uint32_t bar) {
    asm volatile("mbarrier.arrive.shared.b64 _, [%0];" :: "r"(bar) : "memory");
}
__device__ __forceinline__ void mbar_wait(uint32_t bar, uint32_t parity) {
    asm volatile(
        "{\n\t.reg .pred P;\n\tWL_%=:\n\t"
        "mbarrier.try_wait.parity.acquire.cta.shared::cta.b64 P, [%0], %1, 0x989680;\n\t"
        "@P bra.uni WD_%=;\n\tbra.uni WL_%=;\n\tWD_%=:\n\t}"
        :: "r"(bar), "r"(parity) : "memory");
}
__device__ __forceinline__ void expect_tx(uint32_t bar, uint32_t bytes) {
    asm volatile("mbarrier.arrive.expect_tx.shared.b64 _, [%0], %1;"
                 :: "r"(bar), "r"(bytes) : "memory");
}
__device__ __forceinline__ void bulk_ld(uint32_t dst, const void* src,
                                        uint32_t bytes, uint32_t bar) {
    asm volatile(
        "cp.async.bulk.shared::cluster.global.mbarrier::complete_tx::bytes "
        "[%0], [%1], %2, [%3];"
        :: "r"(dst), "l"(src), "r"(bytes), "r"(bar) : "memory");
}
__device__ __forceinline__ void bulk_st(void* dst, uint32_t src, uint32_t bytes) {
    asm volatile("cp.async.bulk.global.shared::cta.bulk_group [%0], [%1], %2;"
        :: "l"(dst), "r"(src), "r"(bytes) : "memory");
}
#define FENCE_ASYNC() asm volatile("fence.proxy.async;" ::: "memory")
__device__ __forceinline__ void ldm_x4(uint32_t* r, uint32_t addr) {
    asm volatile("ldmatrix.sync.aligned.m8n8.x4.shared.b16 {%0,%1,%2,%3}, [%4];"
        : "=r"(r[0]), "=r"(r[1]), "=r"(r[2]), "=r"(r[3]) : "r"(addr));
}
__device__ __forceinline__ void mma16816(float* c, const uint32_t* a, const uint32_t* b) {
    asm volatile(
        "mma.sync.aligned.m16n8k16.row.col.f32.f16.f16.f32 "
        "{%0,%1,%2,%3}, {%4,%5,%6,%7}, {%8,%9}, {%0,%1,%2,%3};\n"
        : "+f"(c[0]), "+f"(c[1]), "+f"(c[2]), "+f"(c[3])
        : "r"(a[0]), "r"(a[1]), "r"(a[2]), "r"(a[3]), "r"(b[0]), "r"(b[1]));
}
__device__ __forceinline__ uint32_t sw64(int row, int q) {
    return (uint32_t)(row * 64 + ((q ^ ((row >> 1) & 3)) << 4));
}
__device__ __forceinline__ float sigm(float x) { return 1.0f / (1.0f + __expf(-x)); }
__device__ __forceinline__ float tanh_f(float x) { return 1.0f - 2.0f / (__expf(2.0f * x) + 1.0f); }

// h-phase slab: A + B from smem (as in R14)
__device__ __forceinline__ void slab_mma_h(
    uint32_t stb, int wm, int wn, int lane, float acc[2][8][4])
{
    const int ar0 = wm * 32 + (lane & 15);
    const int br0 = wn * 64 + (lane & 7) + ((lane >> 4) << 3);
    const int aq  = lane >> 4;
    const int bq  = (lane >> 3) & 1;
    const uint32_t bb = stb + A_TILE_B;
    #pragma unroll
    for (int kk = 0; kk < 2; ++kk) {
        uint32_t ra[2][4];
        ldm_x4(ra[0], stb + sw64(ar0,      kk * 2 + aq));
        ldm_x4(ra[1], stb + sw64(ar0 + 16, kk * 2 + aq));
        #pragma unroll
        for (int p = 0; p < 4; ++p) {
            uint32_t rb[4];
            ldm_x4(rb, bb + sw64(br0 + p * 16, kk * 2 + bq));
            mma16816(acc[0][2 * p],     ra[0], rb);
            mma16816(acc[0][2 * p + 1], ra[0], rb + 2);
            mma16816(acc[1][2 * p],     ra[1], rb);
            mma16816(acc[1][2 * p + 1], ra[1], rb + 2);
        }
    }
}

// x-phase slab: A from registers (LDG-prefetched fragments), B from smem
__device__ __forceinline__ void slab_mma_x(
    const uint4 a[2][2], uint32_t stb, int wn, int lane, float acc[2][8][4])
{
    const int br0 = wn * 64 + (lane & 7) + ((lane >> 4) << 3);
    const int bq  = (lane >> 3) & 1;
    const uint32_t bb = stb + A_TILE_B;
    #pragma unroll
    for (int kk = 0; kk < 2; ++kk) {
        #pragma unroll
        for (int p = 0; p < 4; ++p) {
            uint32_t rb[4];
            ldm_x4(rb, bb + sw64(br0 + p * 16, kk * 2 + bq));
            mma16816(acc[0][2 * p],     (const uint32_t*)&a[kk][0], rb);
            mma16816(acc[0][2 * p + 1], (const uint32_t*)&a[kk][0], rb + 2);
            mma16816(acc[1][2 * p],     (const uint32_t*)&a[kk][1], rb);
            mma16816(acc[1][2 * p + 1], (const uint32_t*)&a[kk][1], rb + 2);
        }
    }
}

// ---------------------------------------------------------------------------
// Prep kernels
// ---------------------------------------------------------------------------
__global__ void prep_weights(
    const float* __restrict__ w_ii, const float* __restrict__ w_hi,
    const float* __restrict__ w_if, const float* __restrict__ w_hf,
    const float* __restrict__ w_ig, const float* __restrict__ w_hg,
    const float* __restrict__ w_io, const float* __restrict__ w_ho)
{
    int idx = blockIdx.x * blockDim.x + threadIdx.x;
    if (idx >= NGC * 128) return;
    const int colp = idx >> 7;
    const int c8   = idx & 127;
    const int n    = colp >> 2;
    const int g    = colp & 3;
    const int slab = c8 >> 2, q = c8 & 3;
    const int k0   = c8 * 8;
    const int nt   = colp >> 8, trow = colp & 255;
    const size_t byteoff = (size_t)nt * (NT_H * 2) + (size_t)slab * B_TILE_B + sw64(trow, q);
    const float* wh = (g == 0) ? w_hi : (g == 1) ? w_hf : (g == 2) ? w_hg : w_ho;
    const float* wx = (g == 0) ? w_ii : (g == 1) ? w_if : (g == 2) ? w_ig : w_io;
    __half vh[8], vx[8];
    #pragma unroll
    for (int j = 0; j < 8; ++j) {
        vh[j] = __float2half_rn(wh[(size_t)(k0 + j) * HID + n]);
        vx[j] = __float2half_rn(wx[(size_t)(k0 + j) * HID + n]);
    }
    *reinterpret_cast<uint4*>(reinterpret_cast<char*>(g_WhT) + byteoff) =
        *reinterpret_cast<const uint4*>(vh);
    *reinterpret_cast<uint4*>(reinterpret_cast<char*>(g_WxT) + byteoff) =
        *reinterpret_cast<const uint4*>(vx);
}

// x -> fragment-linear: thread = one 16B fragment chunk (kk,mt) of (mtile,s,slab,wm,lane)
__global__ void prep_x(const float* __restrict__ x)
{
    size_t idx = (size_t)blockIdx.x * blockDim.x + threadIdx.x;
    if (idx >= (size_t)8 * SLEN * 32 * 4 * 32 * 4) return;   // 16.78M chunks
    const int c4    = (int)(idx & 3);          // kk*2+mt
    const int lane  = (int)((idx >> 2) & 31);
    const int wm    = (int)((idx >> 7) & 3);
    const int slab  = (int)((idx >> 9) & 31);
    const int s     = (int)((idx >> 14) & 127);
    const int mtile = (int)(idx >> 21);
    const int kk = c4 >> 1, mt = c4 & 1;

    const int r  = wm * 32 + mt * 16 + (lane >> 2);
    const int b0 = mtile * 128 + r;
    const int b1 = b0 + 8;
    const int c0 = slab * 32 + kk * 16 + (lane & 3) * 2;
    const int c1 = c0 + 8;

    const float* x0 = x + ((size_t)b0 * SLEN + s) * HID;
    const float* x1 = x + ((size_t)b1 * SLEN + s) * HID;
    __half2 a0 = __floats2half2_rn(x0[c0], x0[c0 + 1]);
    __half2 a1 = __floats2half2_rn(x1[c0], x1[c0 + 1]);
    __half2 a2 = __floats2half2_rn(x0[c1], x0[c1 + 1]);
    __half2 a3 = __floats2half2_rn(x1[c1], x1[c1 + 1]);
    uint4 v;
    v.x = *reinterpret_cast<uint32_t*>(&a0);
    v.y = *reinterpret_cast<uint32_t*>(&a1);
    v.z = *reinterpret_cast<uint32_t*>(&a2);
    v.w = *reinterpret_cast<uint32_t*>(&a3);
    const size_t byteoff = ((size_t)(mtile * SLEN + s) * NSX + slab) * (size_t)A_TILE_B
                         + wm * 2048 + lane * 64 + c4 * 16;
    *reinterpret_cast<uint4*>(reinterpret_cast<char*>(g_XT) + byteoff) = v;
}

__global__ void prep_state(
    const float* __restrict__ b_ii, const float* __restrict__ b_hi,
    const float* __restrict__ b_if, const float* __restrict__ b_hf,
    const float* __restrict__ b_ig, const float* __restrict__ b_hg,
    const float* __restrict__ b_io, const float* __restrict__ b_ho)
{
    int idx = blockIdx.x * blockDim.x + threadIdx.x;
    if (idx < 8) g_cnt[idx] = 0u;
    if (idx < NGC) {
        int n = idx >> 2, g = idx & 3;
        const float* bi = (g == 0) ? b_ii : (g == 1) ? b_if : (g == 2) ? b_ig : b_io;
        const float* bh = (g == 0) ? b_hi : (g == 1) ? b_hf : (g == 2) ? b_hg : b_ho;
        g_bias[idx] = bi[n] + bh[n];
    }
}

// ---------------------------------------------------------------------------
// Persistent kernel: 128 CTAs, 544 threads (16 consumer warps + producer warp)
// ---------------------------------------------------------------------------
__global__ __launch_bounds__(THREADS, 1) void lstm_persistent(
    float* __restrict__ h_g, float* __restrict__ c_g)
{
    extern __shared__ __align__(128) char smem[];
    __shared__ __align__(8) uint64_t barr[5];
    __shared__ __align__(16) float sbias[BN];

    const int tid  = threadIdx.x;
    const int lane = tid & 31;
    const int warp = tid >> 5;
    const int wm   = warp >> 2;
    const int wn   = warp & 3;
    const int bm   = blockIdx.y * BM;
    const uint32_t sbase = smem_u32(smem);
    const uint32_t fb0   = smem_u32(barr);
    const int n0g = blockIdx.x * 64;

    if (tid == 0) {
        #pragma unroll
        for (int i = 0; i < 2; ++i) {
            mbar_init(fb0 + i * 8, 1);
            mbar_init(fb0 + 16 + i * 8, NCW);
        }
        mbar_init(fb0 + 32, NCW);
        FENCE_ASYNC();
    }
    if (tid < BN) sbias[tid] = g_bias[blockIdx.x * BN + tid];
    __syncthreads();

    if (warp < NCW) {
        // ================= CONSUMERS: free-running =================
        float acc[2][8][4];
        #pragma unroll
        for (int a = 0; a < 2; ++a)
            #pragma unroll
            for (int b = 0; b < 8; ++b)
                #pragma unroll
                for (int v = 0; v < 4; ++v) acc[a][b][v] = 0.0f;
        float c_reg[16];
        #pragma unroll
        for (int i = 0; i < 16; ++i) c_reg[i] = 0.0f;

        // x fragment base for this CTA's m-tile + this warp/lane
        const char* xfrag = reinterpret_cast<const char*>(g_XT)
            + (size_t)blockIdx.y * SLEN * NSX * A_TILE_B + wm * 2048 + lane * 64;
        uint4 abuf[2][2][2];   // [parity][kk][mt]

        auto lda = [&](int ss, int j, int par) {
            const uint4* p = reinterpret_cast<const uint4*>(
                xfrag + ((size_t)ss * NSX + j) * A_TILE_B);
            abuf[par][0][0] = __ldg(p + 0);
            abuf[par][0][1] = __ldg(p + 1);
            abuf[par][1][0] = __ldg(p + 2);
            abuf[par][1][1] = __ldg(p + 3);
        };

        unsigned cg = 0;
        const int odd = lane & 1;
        const int rb  = wm * 32 + (lane >> 2) + (odd ? 8 : 0);

        lda(0, 0, 0);          // prefetch first x slab

        for (int s = 0; s < SLEN; ++s) {
            // ---- x phase: 8 groups, A from registers ----
            for (int g = 0; g < NSX / GRP; ++g) {
                const int slot = cg & 1;
                mbar_wait(fb0 + slot * 8, (cg >> 1) & 1);
                const uint32_t gbase = sbase + slot * GROUP_B;
                #pragma unroll
                for (int sl = 0; sl < GRP; ++sl) {
                    const int j = g * GRP + sl;
                    const int par = j & 1;
                    if (j + 1 < NSX)           lda(s, j + 1, (j + 1) & 1);
                    else if (s + 1 < SLEN)     lda(s + 1, 0, 0);
                    slab_mma_x(abuf[par], gbase + sl * STAGE_B, wn, lane, acc);
                }
                if (lane == 0) mbar_arrive(fb0 + 16 + slot * 8);
                ++cg;
            }
            // ---- h phase: 8 groups (skipped at s=0), A from smem ----
            if (s > 0) {
                for (int g = 0; g < NSX / GRP; ++g) {
                    const int slot = cg & 1;
                    mbar_wait(fb0 + slot * 8, (cg >> 1) & 1);
                    const uint32_t gbase = sbase + slot * GROUP_B;
                    #pragma unroll
                    for (int sl = 0; sl < GRP; ++sl)
                        slab_mma_h(gbase + sl * STAGE_B, wm, wn, lane, acc);
                    if (lane == 0) mbar_arrive(fb0 + 16 + slot * 8);
                    ++cg;
                }
            }
            // ---- fused cell update -> hstg[s&1] ----
            char* hstg = smem + HSTG_OFF + (s & 1) * HSTG_B;
            const bool last = (s == SLEN - 1);
            #pragma unroll
            for (int mt = 0; mt < 2; ++mt) {
                #pragma unroll
                for (int nt = 0; nt < 8; ++nt) {
                    float v0 = acc[mt][nt][0], v1 = acc[mt][nt][1];
                    float v2 = acc[mt][nt][2], v3 = acc[mt][nt][3];
                    const float s0 = __shfl_xor_sync(0xffffffffu, v0, 1);
                    const float s1 = __shfl_xor_sync(0xffffffffu, v1, 1);
                    const float s2 = __shfl_xor_sync(0xffffffffu, v2, 1);
                    const float s3 = __shfl_xor_sync(0xffffffffu, v3, 1);
                    const int row = rb + mt * 16;
                    const int u   = wn * 16 + nt * 2 + ((lane & 3) >> 1);
                    float xi = odd ? s2 : v0;
                    float xf = odd ? s3 : v1;
                    float xg = odd ? v2 : s0;
                    float xo = odd ? v3 : s1;
                    const float4 bv = *reinterpret_cast<const float4*>(&sbias[4 * u]);
                    xi += bv.x; xf += bv.y; xg += bv.z; xo += bv.w;
                    const float ig = sigm(xi), fg = sigm(xf);
                    const float gg = tanh_f(xg), og = sigm(xo);
                    const float cc = fg * c_reg[mt * 8 + nt] + ig * gg;
                    c_reg[mt * 8 + nt] = cc;
                    const float hh = og * tanh_f(cc);
                    *reinterpret_cast<__half*>(hstg + (u >> 5) * A_TILE_B
                        + sw64(row, (u & 31) >> 3) + (u & 7) * 2)
                        = __float2half_rn(hh);
                    if (last) {
                        const size_t gi = (size_t)(bm + row) * HID + n0g + u;
                        h_g[gi] = hh;
                        c_g[gi] = cc;
                    }
                    acc[mt][nt][0] = 0.0f; acc[mt][nt][1] = 0.0f;
                    acc[mt][nt][2] = 0.0f; acc[mt][nt][3] = 0.0f;
                }
            }
            __syncwarp();
            if (lane == 0) mbar_arrive(fb0 + 32);
        }
    } else if (tid == NCW * 32) {
        // ================= PRODUCER =================
        int is = 0, ij = 0, bar_seen = 0;
        unsigned pg = 0;
        unsigned* my_cnt = &g_cnt[blockIdx.y];

        // prologue: groups 0,1 = x slabs 0..7 of step 0 (B only)
        #pragma unroll
        for (int i = 0; i < 2; ++i) {
            expect_tx(fb0 + i * 8, GRP * B_TILE_B);
            #pragma unroll
            for (int sl = 0; sl < GRP; ++sl) {
                const int j = i * GRP + sl;
                bulk_ld(sbase + i * GROUP_B + sl * STAGE_B + A_TILE_B,
                        g_WxT + (size_t)blockIdx.x * NT_H + (size_t)j * B_SLAB_H,
                        B_TILE_B, fb0 + i * 8);
            }
        }
        ij = 2 * GRP;

        for (int s = 0; s < SLEN; ++s) {
            const int NG = (s == 0) ? (NSX / GRP) : (2 * NSX / GRP);
            for (int g = 0; g < NG; ++g) {
                const int slot = pg & 1;
                mbar_wait(fb0 + 16 + slot * 8, (pg >> 1) & 1);
                if (is < SLEN) {
                    const uint32_t rbase = sbase + slot * GROUP_B;
                    const bool xphase = (ij < NSX);
                    expect_tx(fb0 + slot * 8,
                              xphase ? GRP * B_TILE_B : GROUP_B);
                    #pragma unroll
                    for (int sl = 0; sl < GRP; ++sl) {
                        if (ij < NSX) {
                            // x slab: B only
                            bulk_ld(rbase + sl * STAGE_B + A_TILE_B,
                                    g_WxT + (size_t)blockIdx.x * NT_H
                                        + (size_t)ij * B_SLAB_H,
                                    B_TILE_B, fb0 + slot * 8);
                        } else {
                            if (bar_seen < is) {
                                const unsigned target = (unsigned)is * ROW_CTAS;
                                unsigned v;
                                do {
                                    asm volatile("ld.acquire.gpu.global.u32 %0, [%1];"
                                                 : "=r"(v) : "l"(my_cnt) : "memory");
                                } while (v < target);
                                FENCE_ASYNC();
                                bar_seen = is;
                            }
                            bulk_ld(rbase + sl * STAGE_B,
                                    g_HaT[is & 1] + (size_t)blockIdx.y * MT_H
                                        + (size_t)(ij - NSX) * A_SLAB_H,
                                    A_TILE_B, fb0 + slot * 8);
                            bulk_ld(rbase + sl * STAGE_B + A_TILE_B,
                                    g_WhT + (size_t)blockIdx.x * NT_H
                                        + (size_t)(ij - NSX) * B_SLAB_H,
                                    B_TILE_B, fb0 + slot * 8);
                        }
                        if (++ij == ((is == 0) ? NSX : 2 * NSX)) { ij = 0; ++is; }
                    }
                }
                ++pg;
            }
            // step boundary: wait epilogue(s), store h slice, arrive row barrier
            if (s + 1 < SLEN) {
                mbar_wait(fb0 + 32, s & 1);
                FENCE_ASYNC();
                bulk_st(g_HaT[(s + 1) & 1] + (size_t)blockIdx.y * MT_H
                            + (size_t)(2 * blockIdx.x) * A_SLAB_H,
                        sbase + HSTG_OFF + (s & 1) * HSTG_B, HSTG_B);
                asm volatile("cp.async.bulk.commit_group;" ::: "memory");
                asm volatile("cp.async.bulk.wait_group 0;" ::: "memory");
                __threadfence();
                atomicAdd(my_cnt, 1u);
            }
        }
    }
}

// ---------------------------------------------------------------------------
extern "C" void kernel_launch(void* const* d_in, const int* in_sizes, int n_in,
                              void* d_out, int out_size)
{
    const float* x = nullptr;
    const float* w[8] = {nullptr};
    const float* b[8] = {nullptr};
    int wi = 0, bi = 0;
    for (int i = 0; i < n_in; ++i) {
        const int sz = in_sizes[i];
        if (sz == HID * HID)      { if (wi < 8) w[wi++] = (const float*)d_in[i]; }
        else if (sz == HID)       { if (bi < 8) b[bi++] = (const float*)d_in[i]; }
        else                      { x = (const float*)d_in[i]; }
    }

    float* h = (float*)d_out;
    float* c = h + (size_t)HID * HID;

    cudaFuncSetAttribute(lstm_persistent, cudaFuncAttributeMaxDynamicSharedMemorySize, SMEM_P);

    prep_weights<<<(NGC * 128 + 255) / 256, 256>>>(
        w[0], w[1], w[2], w[3], w[4], w[5], w[6], w[7]);
    {
        const size_t total = (size_t)8 * SLEN * 32 * 4 * 32 * 4;   // 16.78M chunks
        prep_x<<<(unsigned)((total + 255) / 256), 256>>>(x);
    }
    prep_state<<<(HID * HID) / 256, 256>>>(
        b[0], b[1], b[2], b[3], b[4], b[5], b[6], b[7]);

    dim3 grid(NGC / BN, HID / BM);            // 16 x 8 = 128 CTAs, 1 per SM
    lstm_persistent<<<grid, THREADS, SMEM_P>>>(h, c);
}

// round 17
// speedup vs baseline: 2.2548x; 2.2548x over previous
#include <cuda_runtime.h>
#include <cuda_fp16.h>
#include <cstdint>
#include <cstddef>

// LSTM: B == H == 1024, S = 128, I = 1024.
// Persistent kernel (R14 architecture). Per step s:
//   gates = x_s @ Wx + h_{s-1} @ Wh + bias   (64 BK=32 slabs: 32 x, 32 h)
// Group-of-4-slab transfers on one tx-mbarrier; producer warp drives bulk
// copies. h-dependency is FINE-GRAINED: per-CTA store flags; each h-group
// waits only on the 2 CTAs that produced its k-columns.
// fp16 single-product mma.sync; col' = 4n+g (i,f,g,o).

#define HID  1024
#define SLEN 128
#define NGC  4096

#define BM 128
#define BN 256
#define BK 32
#define NSX 32               // x slabs per step (= h slabs per step)
#define GRP 4                // slabs per transfer group

#define A_TILE_B 8192        // 128 x 32 fp16
#define B_TILE_B 16384       // 256 x 32 fp16
#define STAGE_B  (A_TILE_B + B_TILE_B)   // 24576
#define GROUP_B  (GRP * STAGE_B)         // 98304
#define RING_B   (2 * GROUP_B)           // 196608
#define HSTG_OFF RING_B
#define HSTG_B   (2 * A_TILE_B)          // CTA's h slice = 16KB
#define SMEM_P   (RING_B + 2 * HSTG_B)   // 229376

#define A_SLAB_H 4096
#define B_SLAB_H 8192
#define MT_H (NSX * A_SLAB_H)   // 131072
#define NT_H (NSX * B_SLAB_H)   // 262144

#define NCW 16
#define THREADS (NCW * 32 + 32)  // 544

// ---- static device scratch (each < 2GB) ----
__device__ __align__(1024) __half g_WhT[(size_t)16 * NT_H];          // 8 MB
__device__ __align__(1024) __half g_WxT[(size_t)16 * NT_H];          // 8 MB
__device__ __align__(1024) __half g_XT[(size_t)8 * SLEN * MT_H];     // 256 MB
__device__ __align__(1024) __half g_HaT[2][(size_t)8 * MT_H];        // 2 MB each
__device__ float g_bias[NGC];
__device__ unsigned g_flags[8][16];   // per (m-row, bx) h-store step counter

// ---- helpers ----
__device__ __forceinline__ uint32_t smem_u32(const void* p) {
    uint32_t a;
    asm("{ .reg .u64 t; cvta.to.shared.u64 t, %1; cvt.u32.u64 %0, t; }" : "=r"(a) : "l"(p));
    return a;
}
__device__ __forceinline__ void mbar_init(uint32_t bar, uint32_t cnt) {
    asm volatile("mbarrier.init.shared.b64 [%0], %1;" :: "r"(bar), "r"(cnt) : "memory");
}
__device__ __forceinline__ void mbar_arrive(uint32_t bar) {
    asm volatile("mbarrier.arrive.shared.b64 _, [%0];" :: "r"(bar) : "memory");
}
__device__ __forceinline__ void mbar_wait(uint32_t bar, uint32_t parity) {
    asm volatile(
        "{\n\t.reg .pred P;\n\tWL_%=:\n\t"
        "mbarrier.try_wait.parity.acquire.cta.shared::cta.b64 P, [%0], %1, 0x989680;\n\t"
        "@P bra.uni WD_%=;\n\tbra.uni WL_%=;\n\tWD_%=:\n\t}"
        :: "r"(bar), "r"(parity) : "memory");
}
__device__ __forceinline__ void expect_tx(uint32_t bar, uint32_t bytes) {
    asm volatile("mbarrier.arrive.expect_tx.shared.b64 _, [%0], %1;"
                 :: "r"(bar), "r"(bytes) : "memory");
}
__device__ __forceinline__ void bulk_ld(uint32_t dst, const void* src,
                                        uint32_t bytes, uint32_t bar) {
    asm volatile(
        "cp.async.bulk.shared::cluster.global.mbarrier::complete_tx::bytes "
        "[%0], [%1], %2, [%3];"
        :: "r"(dst), "l"(src), "r"(bytes), "r"(bar) : "memory");
}
__device__ __forceinline__ void bulk_st(void* dst, uint32_t src, uint32_t bytes) {
    asm volatile("cp.async.bulk.global.shared::cta.bulk_group [%0], [%1], %2;"
        :: "l"(dst), "r"(src), "r"(bytes) : "memory");
}
#define FENCE_ASYNC() asm volatile("fence.proxy.async;" ::: "memory")
__device__ __forceinline__ void ldm_x4(uint32_t* r, uint32_t addr) {
    asm volatile("ldmatrix.sync.aligned.m8n8.x4.shared.b16 {%0,%1,%2,%3}, [%4];"
        : "=r"(r[0]), "=r"(r[1]), "=r"(r[2]), "=r"(r[3]) : "r"(addr));
}
__device__ __forceinline__ void mma16816(float* c, const uint32_t* a, const uint32_t* b) {
    asm volatile(
        "mma.sync.aligned.m16n8k16.row.col.f32.f16.f16.f32 "
        "{%0,%1,%2,%3}, {%4,%5,%6,%7}, {%8,%9}, {%0,%1,%2,%3};\n"
        : "+f"(c[0]), "+f"(c[1]), "+f"(c[2]), "+f"(c[3])
        : "r"(a[0]), "r"(a[1]), "r"(a[2]), "r"(a[3]), "r"(b[0]), "r"(b[1]));
}
__device__ __forceinline__ uint32_t sw64(int row, int q) {
    return (uint32_t)(row * 64 + ((q ^ ((row >> 1) & 3)) << 4));
}
__device__ __forceinline__ float sigm(float x) { return 1.0f / (1.0f + __expf(-x)); }
__device__ __forceinline__ float tanh_f(float x) { return 1.0f - 2.0f / (__expf(2.0f * x) + 1.0f); }
__device__ __forceinline__ float tanh_ap(float x) {
    float y; asm("tanh.approx.f32 %0, %1;" : "=f"(y) : "f"(x)); return y;
}
__device__ __forceinline__ float sigm_ap(float x) {   // i/o gates only
    return fmaf(0.5f, tanh_ap(0.5f * x), 0.5f);
}

// One BK=32 slab for this warp (32 HMMA, 12 LDSM.x4); 32x64 warp tile.
__device__ __forceinline__ void slab_mma(
    uint32_t stb, int wm, int wn, int lane, float acc[2][8][4])
{
    const int ar0 = wm * 32 + (lane & 15);
    const int br0 = wn * 64 + (lane & 7) + ((lane >> 4) << 3);
    const int aq  = lane >> 4;
    const int bq  = (lane >> 3) & 1;
    const uint32_t bb = stb + A_TILE_B;
    #pragma unroll
    for (int kk = 0; kk < 2; ++kk) {
        uint32_t ra[2][4];
        ldm_x4(ra[0], stb + sw64(ar0,      kk * 2 + aq));
        ldm_x4(ra[1], stb + sw64(ar0 + 16, kk * 2 + aq));
        #pragma unroll
        for (int p = 0; p < 4; ++p) {
            uint32_t rb[4];
            ldm_x4(rb, bb + sw64(br0 + p * 16, kk * 2 + bq));
            mma16816(acc[0][2 * p],     ra[0], rb);
            mma16816(acc[0][2 * p + 1], ra[0], rb + 2);
            mma16816(acc[1][2 * p],     ra[1], rb);
            mma16816(acc[1][2 * p + 1], ra[1], rb + 2);
        }
    }
}

// ---------------------------------------------------------------------------
// Prep kernels (tiled, pre-swizzled; 64B rows, BK=32 slabs)
// ---------------------------------------------------------------------------
__global__ void prep_weights(
    const float* __restrict__ w_ii, const float* __restrict__ w_hi,
    const float* __restrict__ w_if, const float* __restrict__ w_hf,
    const float* __restrict__ w_ig, const float* __restrict__ w_hg,
    const float* __restrict__ w_io, const float* __restrict__ w_ho)
{
    int idx = blockIdx.x * blockDim.x + threadIdx.x;
    if (idx >= NGC * 128) return;
    const int colp = idx >> 7;           // col' = 4n+g
    const int c8   = idx & 127;          // 16B chunk; k0 = c8*8
    const int n    = colp >> 2;
    const int g    = colp & 3;
    const int slab = c8 >> 2, q = c8 & 3;
    const int k0   = c8 * 8;
    const int nt   = colp >> 8, trow = colp & 255;
    const size_t byteoff = (size_t)nt * (NT_H * 2) + (size_t)slab * B_TILE_B + sw64(trow, q);
    const float* wh = (g == 0) ? w_hi : (g == 1) ? w_hf : (g == 2) ? w_hg : w_ho;
    const float* wx = (g == 0) ? w_ii : (g == 1) ? w_if : (g == 2) ? w_ig : w_io;
    __half vh[8], vx[8];
    #pragma unroll
    for (int j = 0; j < 8; ++j) {
        vh[j] = __float2half_rn(wh[(size_t)(k0 + j) * HID + n]);
        vx[j] = __float2half_rn(wx[(size_t)(k0 + j) * HID + n]);
    }
    *reinterpret_cast<uint4*>(reinterpret_cast<char*>(g_WhT) + byteoff) =
        *reinterpret_cast<const uint4*>(vh);
    *reinterpret_cast<uint4*>(reinterpret_cast<char*>(g_WxT) + byteoff) =
        *reinterpret_cast<const uint4*>(vx);
}

__global__ void prep_x(const float* __restrict__ x)
{
    size_t idx = (size_t)blockIdx.x * blockDim.x + threadIdx.x;
    if (idx >= (size_t)HID * SLEN * 128) return;
    const int b   = (int)(idx >> 14);
    const int s   = (int)((idx >> 7) & 127);
    const int c8  = (int)(idx & 127);
    const int slab = c8 >> 2, q = c8 & 3;
    const float* src = x + ((size_t)b * SLEN + s) * HID + c8 * 8;
    __half v[8];
    #pragma unroll
    for (int j = 0; j < 8; ++j) v[j] = __float2half_rn(src[j]);
    const size_t byteoff =
        ((size_t)((b >> 7) * SLEN + s) * NSX + slab) * A_TILE_B + sw64(b & 127, q);
    *reinterpret_cast<uint4*>(reinterpret_cast<char*>(g_XT) + byteoff) =
        *reinterpret_cast<const uint4*>(v);
}

__global__ void prep_state(
    const float* __restrict__ b_ii, const float* __restrict__ b_hi,
    const float* __restrict__ b_if, const float* __restrict__ b_hf,
    const float* __restrict__ b_ig, const float* __restrict__ b_hg,
    const float* __restrict__ b_io, const float* __restrict__ b_ho)
{
    int idx = blockIdx.x * blockDim.x + threadIdx.x;
    if (idx < 128) (&g_flags[0][0])[idx] = 0u;
    if (idx < NGC) {
        int n = idx >> 2, g = idx & 3;
        const float* bi = (g == 0) ? b_ii : (g == 1) ? b_if : (g == 2) ? b_ig : b_io;
        const float* bh = (g == 0) ? b_hi : (g == 1) ? b_hf : (g == 2) ? b_hg : b_ho;
        g_bias[idx] = bi[n] + bh[n];
    }
}

// ---------------------------------------------------------------------------
// Persistent kernel: 128 CTAs, 544 threads (16 consumer warps + producer warp)
// barriers: full[0..1] @ fb0+{0,8}, empty[0..1] @ fb0+{16,24}, epi @ fb0+32
// ---------------------------------------------------------------------------
__global__ __launch_bounds__(THREADS, 1) void lstm_persistent(
    float* __restrict__ h_g, float* __restrict__ c_g)
{
    extern __shared__ __align__(128) char smem[];
    __shared__ __align__(8) uint64_t barr[5];
    __shared__ __align__(16) float sbias[BN];

    const int tid  = threadIdx.x;
    const int lane = tid & 31;
    const int warp = tid >> 5;
    const int wm   = warp >> 2;
    const int wn   = warp & 3;
    const int bm   = blockIdx.y * BM;
    const uint32_t sbase = smem_u32(smem);
    const uint32_t fb0   = smem_u32(barr);
    const int n0g = blockIdx.x * 64;

    if (tid == 0) {
        #pragma unroll
        for (int i = 0; i < 2; ++i) {
            mbar_init(fb0 + i * 8, 1);        // group-full (tx)
            mbar_init(fb0 + 16 + i * 8, NCW); // group-empty
        }
        mbar_init(fb0 + 32, NCW);             // epilogue-done
        FENCE_ASYNC();
    }
    if (tid < BN) sbias[tid] = g_bias[blockIdx.x * BN + tid];
    __syncthreads();

    if (warp < NCW) {
        // ================= CONSUMERS: free-running =================
        float acc[2][8][4];
        #pragma unroll
        for (int a = 0; a < 2; ++a)
            #pragma unroll
            for (int b = 0; b < 8; ++b)
                #pragma unroll
                for (int v = 0; v < 4; ++v) acc[a][b][v] = 0.0f;
        float c_reg[16];
        #pragma unroll
        for (int i = 0; i < 16; ++i) c_reg[i] = 0.0f;

        unsigned cg = 0;
        const int odd = lane & 1;
        const int rb  = wm * 32 + (lane >> 2) + (odd ? 8 : 0);

        for (int s = 0; s < SLEN; ++s) {
            const int NG = (s == 0) ? (NSX / GRP) : (2 * NSX / GRP);  // 8 or 16
            for (int g = 0; g < NG; ++g) {
                const int slot = cg & 1;
                mbar_wait(fb0 + slot * 8, (cg >> 1) & 1);
                const uint32_t gbase = sbase + slot * GROUP_B;
                #pragma unroll
                for (int sl = 0; sl < GRP; ++sl)
                    slab_mma(gbase + sl * STAGE_B, wm, wn, lane, acc);
                if (lane == 0) mbar_arrive(fb0 + 16 + slot * 8);
                ++cg;
            }
            // fused cell update -> hstg[s&1]
            char* hstg = smem + HSTG_OFF + (s & 1) * HSTG_B;
            const bool last = (s == SLEN - 1);
            #pragma unroll
            for (int mt = 0; mt < 2; ++mt) {
                #pragma unroll
                for (int nt = 0; nt < 8; ++nt) {
                    float v0 = acc[mt][nt][0], v1 = acc[mt][nt][1];
                    float v2 = acc[mt][nt][2], v3 = acc[mt][nt][3];
                    const float s0 = __shfl_xor_sync(0xffffffffu, v0, 1);
                    const float s1 = __shfl_xor_sync(0xffffffffu, v1, 1);
                    const float s2 = __shfl_xor_sync(0xffffffffu, v2, 1);
                    const float s3 = __shfl_xor_sync(0xffffffffu, v3, 1);
                    const int row = rb + mt * 16;
                    const int u   = wn * 16 + nt * 2 + ((lane & 3) >> 1);
                    float xi = odd ? s2 : v0;
                    float xf = odd ? s3 : v1;
                    float xg = odd ? v2 : s0;
                    float xo = odd ? v3 : s1;
                    const float4 bv = *reinterpret_cast<const float4*>(&sbias[4 * u]);
                    xi += bv.x; xf += bv.y; xg += bv.z; xo += bv.w;
                    const float ig = sigm_ap(xi);      // approx ok (non-compounding)
                    const float fg = sigm(xf);         // exact (multiplies c)
                    const float gg = tanh_f(xg);       // exact
                    const float og = sigm_ap(xo);      // approx ok
                    const float cc = fg * c_reg[mt * 8 + nt] + ig * gg;
                    c_reg[mt * 8 + nt] = cc;
                    const float hh = og * tanh_f(cc);
                    *reinterpret_cast<__half*>(hstg + (u >> 5) * A_TILE_B
                        + sw64(row, (u & 31) >> 3) + (u & 7) * 2)
                        = __float2half_rn(hh);
                    if (last) {
                        const size_t gi = (size_t)(bm + row) * HID + n0g + u;
                        h_g[gi] = hh;
                        c_g[gi] = cc;
                    }
                    acc[mt][nt][0] = 0.0f; acc[mt][nt][1] = 0.0f;
                    acc[mt][nt][2] = 0.0f; acc[mt][nt][3] = 0.0f;
                }
            }
            __syncwarp();
            if (lane == 0) mbar_arrive(fb0 + 32);   // epilogue(s) done
        }
    } else if (tid == NCW * 32) {
        // ================= PRODUCER =================
        int is = 0, ij = 0;
        unsigned pg = 0;
        unsigned flag_seen[2] = {0u, 0u};   // last observed per relevant flag pair slot

        // prologue: groups 0,1 = x slabs 0..7 of step 0
        #pragma unroll
        for (int i = 0; i < 2; ++i) {
            expect_tx(fb0 + i * 8, GROUP_B);
            #pragma unroll
            for (int sl = 0; sl < GRP; ++sl) {
                const int j = i * GRP + sl;
                bulk_ld(sbase + i * GROUP_B + sl * STAGE_B,
                        g_XT + ((size_t)(blockIdx.y * SLEN) * NSX + j) * A_SLAB_H,
                        A_TILE_B, fb0 + i * 8);
                bulk_ld(sbase + i * GROUP_B + sl * STAGE_B + A_TILE_B,
                        g_WxT + (size_t)blockIdx.x * NT_H + (size_t)j * B_SLAB_H,
                        B_TILE_B, fb0 + i * 8);
            }
        }
        ij = 2 * GRP;

        for (int s = 0; s < SLEN; ++s) {
            const int NG = (s == 0) ? (NSX / GRP) : (2 * NSX / GRP);
            for (int g = 0; g < NG; ++g) {
                const int slot = pg & 1;
                mbar_wait(fb0 + 16 + slot * 8, (pg >> 1) & 1);
                if (is < SLEN) {
                    const uint32_t rbase = sbase + slot * GROUP_B;
                    // Fine-grained h-dependency: h-group g' needs CTAs 2g',2g'+1
                    if (ij >= NSX) {
                        const int hg = (ij - NSX) >> 2;       // 0..7
                        const unsigned need = (unsigned)is;
                        #pragma unroll
                        for (int t = 0; t < 2; ++t) {
                            volatile unsigned* fl = &g_flags[blockIdx.y][2 * hg + t];
                            unsigned v;
                            do {
                                asm volatile("ld.acquire.gpu.global.u32 %0, [%1];"
                                             : "=r"(v) : "l"((const unsigned*)fl) : "memory");
                            } while (v < need);
                        }
                        FENCE_ASYNC();
                        (void)flag_seen;
                    }
                    expect_tx(fb0 + slot * 8, GROUP_B);
                    #pragma unroll
                    for (int sl = 0; sl < GRP; ++sl) {
                        const __half *aT, *bT;
                        if (ij < NSX) {
                            aT = g_XT + ((size_t)(blockIdx.y * SLEN + is) * NSX + ij) * A_SLAB_H;
                            bT = g_WxT + (size_t)blockIdx.x * NT_H + (size_t)ij * B_SLAB_H;
                        } else {
                            aT = g_HaT[is & 1] + (size_t)blockIdx.y * MT_H
                               + (size_t)(ij - NSX) * A_SLAB_H;
                            bT = g_WhT + (size_t)blockIdx.x * NT_H
                               + (size_t)(ij - NSX) * B_SLAB_H;
                        }
                        bulk_ld(rbase + sl * STAGE_B,            aT, A_TILE_B, fb0 + slot * 8);
                        bulk_ld(rbase + sl * STAGE_B + A_TILE_B, bT, B_TILE_B, fb0 + slot * 8);
                        if (++ij == ((is == 0) ? NSX : 2 * NSX)) { ij = 0; ++is; }
                    }
                }
                ++pg;
            }
            // step boundary: wait epilogue(s), store h slice, publish flag
            if (s + 1 < SLEN) {
                mbar_wait(fb0 + 32, s & 1);
                FENCE_ASYNC();
                bulk_st(g_HaT[(s + 1) & 1] + (size_t)blockIdx.y * MT_H
                            + (size_t)(2 * blockIdx.x) * A_SLAB_H,
                        sbase + HSTG_OFF + (s & 1) * HSTG_B, HSTG_B);
                asm volatile("cp.async.bulk.commit_group;" ::: "memory");
                asm volatile("cp.async.bulk.wait_group 0;" ::: "memory");
                __threadfence();
                asm volatile("st.release.gpu.global.u32 [%0], %1;"
                             :: "l"(&g_flags[blockIdx.y][blockIdx.x]),
                                "r"((unsigned)(s + 1)) : "memory");
            }
        }
    }
}

// ---------------------------------------------------------------------------
extern "C" void kernel_launch(void* const* d_in, const int* in_sizes, int n_in,
                              void* d_out, int out_size)
{
    const float* x = nullptr;
    const float* w[8] = {nullptr};
    const float* b[8] = {nullptr};
    int wi = 0, bi = 0;
    for (int i = 0; i < n_in; ++i) {
        const int sz = in_sizes[i];
        if (sz == HID * HID)      { if (wi < 8) w[wi++] = (const float*)d_in[i]; }
        else if (sz == HID)       { if (bi < 8) b[bi++] = (const float*)d_in[i]; }
        else                      { x = (const float*)d_in[i]; }
    }

    float* h = (float*)d_out;
    float* c = h + (size_t)HID * HID;

    cudaFuncSetAttribute(lstm_persistent, cudaFuncAttributeMaxDynamicSharedMemorySize, SMEM_P);

    prep_weights<<<(NGC * 128 + 255) / 256, 256>>>(
        w[0], w[1], w[2], w[3], w[4], w[5], w[6], w[7]);
    {
        const size_t total = (size_t)HID * SLEN * 128;
        prep_x<<<(unsigned)((total + 255) / 256), 256>>>(x);
    }
    prep_state<<<(HID * HID) / 256, 256>>>(
        b[0], b[1], b[2], b[3], b[4], b[5], b[6], b[7]);

    dim3 grid(NGC / BN, HID / BM);            // 16 x 8 = 128 CTAs, 1 per SM
    lstm_persistent<<<grid, THREADS, SMEM_P>>>(h, c);
}